// round 9
// baseline (speedup 1.0000x reference)
#include <cuda_runtime.h>
#include <cuda_bf16.h>
#include <math.h>
#include <stdint.h>

#define BB 8
#define NQ 2048
#define NK 2048
#define DD 256
#define MP 1152              // padded half-row count (9*128), rows 0..1024 real

// ---------------- static gmem scratch ----------------
__device__ __align__(256) int8_t g_CQ0[MP * 1024], g_CQ1[MP * 1024];
__device__ float g_sC[MP];
__device__ __align__(256) int8_t g_qQ0[BB * NQ * DD], g_qQ1[BB * NQ * DD];
__device__ float g_sQ[BB * NQ];
__device__ __align__(256) int8_t g_kQ0[BB * NK * DD], g_kQ1[BB * NK * DD];
__device__ float g_sK[BB * NK];
__device__ __align__(256) int8_t g_wqQ0[DD * DD], g_wqQ1[DD * DD];
__device__ float g_sWQ[DD];
__device__ __align__(256) int8_t g_wkQ0[DD * DD], g_wkQ1[DD * DD];
__device__ float g_sWK[DD];
__device__ float g_qpT[DD * BB * NQ];                     // qprojT fp32 [256][16384]
__device__ __align__(256) int8_t g_qpFQ0[DD * BB * 1024], g_qpFQ1[DD * BB * 1024];
__device__ float g_sQPF[BB * DD];
__device__ float g_q1024[BB * DD];
__device__ float g_kpf[BB * NK * DD];                     // kproj fp32
__device__ __align__(256) int8_t g_kpQ0[BB * NK * DD], g_kpQ1[BB * NK * DD];
__device__ float g_sKP[BB * NK];
__device__ __align__(256) int8_t g_qfQ0[BB * MP * DD], g_qfQ1[BB * MP * DD];
__device__ float g_sQF[BB * MP];
__device__ float g_vTf[BB * DD * NK];                     // key^T fp32
__device__ __align__(256) int8_t g_vTQ0[BB * DD * NK], g_vTQ1[BB * DD * NK];
__device__ float g_sVT[BB * DD];
__device__ float g_scores[(size_t)BB * MP * NK];
__device__ __align__(256) int8_t g_pQ0[(size_t)BB * MP * NK], g_pQ1[(size_t)BB * MP * NK];
__device__ float g_sP[BB * MP];
__device__ float g_op[16 * MP * DD];                      // split-K partials

// ---------------- helpers ----------------
__device__ __forceinline__ unsigned smem_u32(const void* p) {
    unsigned a;
    asm("{ .reg .u64 t; cvta.to.shared.u64 t, %1; cvt.u32.u64 %0, t; }"
        : "=r"(a) : "l"(p));
    return a;
}
__device__ __forceinline__ void ldsm4(unsigned r[4], unsigned addr) {
    asm volatile("ldmatrix.sync.aligned.m8n8.x4.shared.b16 {%0,%1,%2,%3}, [%4];"
                 : "=r"(r[0]), "=r"(r[1]), "=r"(r[2]), "=r"(r[3]) : "r"(addr));
}
__device__ __forceinline__ void imma16832(int d[4], const unsigned a[4],
                                          unsigned b0, unsigned b1) {
    asm volatile(
        "mma.sync.aligned.m16n8k32.row.col.s32.s8.s8.s32 "
        "{%0,%1,%2,%3}, {%4,%5,%6,%7}, {%8,%9}, {%0,%1,%2,%3};"
        : "+r"(d[0]), "+r"(d[1]), "+r"(d[2]), "+r"(d[3])
        : "r"(a[0]), "r"(a[1]), "r"(a[2]), "r"(a[3]), "r"(b0), "r"(b1));
}
__device__ __forceinline__ void cpa(unsigned dst, const void* src) {
    asm volatile("cp.async.cg.shared.global [%0], [%1], 16;" :: "r"(dst), "l"(src));
}
// 2-plane int8 quantization: x ~ s*(q0 + q1/256), inv = 1/s
// q1 uses the FULL int8 range (residual in [-0.5,0.5] * 256 -> [-128,128], clamp +128)
__device__ __forceinline__ void quant2(float v, float inv, int8_t& q0, int8_t& q1) {
    float x = v * inv;
    float r0 = rintf(x);
    q0 = (int8_t)(int)r0;
    int i1 = (int)rintf((x - r0) * 256.0f);
    q1 = (int8_t)(i1 > 127 ? 127 : i1);
}
// block max-reduce over 256 threads (returns to all threads)
__device__ __forceinline__ float blockmax256(float v, float* red) {
    int t = threadIdx.x;
#pragma unroll
    for (int o = 16; o > 0; o >>= 1) v = fmaxf(v, __shfl_xor_sync(0xffffffffu, v, o));
    if ((t & 31) == 0) red[t >> 5] = v;
    __syncthreads();
    float m = red[0];
#pragma unroll
    for (int i = 1; i < 8; i++) m = fmaxf(m, red[i]);
    return m;
}

// smem: 2 stages x 64KB; stage: A0 0 | A1 16K | B0 32K | B1 48K. 128B rows, XOR8 swizzle.
#define SMI_BYTES (2 * 65536)

// ---------------- prep kernels ----------------
// generic per-row 2-plane int8 quantization; grid.x = nrows, 256 threads, L % 256 == 0
__global__ void rowquant_kernel(const float* __restrict__ src,
                                int8_t* __restrict__ q0, int8_t* __restrict__ q1,
                                float* __restrict__ sOut, int L) {
    __shared__ float red[8];
    size_t row = blockIdx.x;
    const float* p = src + row * (size_t)L;
    int t = threadIdx.x;
    float mx = 0.0f;
    for (int i = t; i < L; i += 256) mx = fmaxf(mx, fabsf(p[i]));
    mx = blockmax256(mx, red);
    mx = fmaxf(mx, 1e-30f);
    float inv = 127.0f / mx;
    for (int i = t; i < L; i += 256) {
        int8_t a, b2;
        quant2(p[i], inv, a, b2);
        q0[row * (size_t)L + i] = a;
        q1[row * (size_t)L + i] = b2;
    }
    if (t == 0) sOut[row] = mx / 127.0f;
}

// cos matrix, quantized directly (row max = 1 -> s = 1/127)
__global__ void cinitq_kernel() {
    int m = blockIdx.x, t = threadIdx.x;
#pragma unroll
    for (int it = 0; it < 4; it++) {
        int k = t + 256 * it;
        float c = cospif((float)((m * k) & 2047) * (1.0f / 1024.0f));
        int8_t a, b2;
        quant2(c, 127.0f, a, b2);
        g_CQ0[m * 1024 + k] = a;
        g_CQ1[m * 1024 + k] = b2;
    }
    if (t == 0) g_sC[m] = 1.0f / 127.0f;
}

__global__ void transpose_kernel(const float* __restrict__ key) {
    __shared__ float ts[32][33];
    int b = blockIdx.z, n0 = blockIdx.x * 32, d0 = blockIdx.y * 32;
    const float* kb = key + (size_t)b * NK * DD;
#pragma unroll
    for (int i = 0; i < 4; i++) {
        int r = threadIdx.y + i * 8;
        ts[r][threadIdx.x] = kb[(size_t)(n0 + r) * DD + d0 + threadIdx.x];
    }
    __syncthreads();
#pragma unroll
    for (int i = 0; i < 4; i++) {
        int d = threadIdx.y + i * 8;
        g_vTf[(size_t)b * DD * NK + (size_t)(d0 + d) * NK + n0 + threadIdx.x] =
            ts[threadIdx.x][d];
    }
}

// fold + quantize: qpF[d][b*1024+k] = qpT[d][b*2048+k] (+ mirror for k>0)
// grid (DD, BB), 256 threads x 4 elems
__global__ void foldq_kernel() {
    __shared__ float red[8];
    int d = blockIdx.x, b = blockIdx.y, t = threadIdx.x;
    const float* src = g_qpT + (size_t)d * (BB * NQ) + b * 2048;
    float v[4];
#pragma unroll
    for (int it = 0; it < 4; it++) {
        int k = t + 256 * it;
        v[it] = src[k] + ((k > 0) ? src[2048 - k] : 0.0f);
    }
    float mx = fmaxf(fmaxf(fabsf(v[0]), fabsf(v[1])), fmaxf(fabsf(v[2]), fabsf(v[3])));
    mx = fmaxf(blockmax256(mx, red), 1e-30f);
    float inv = 127.0f / mx;
    size_t dst = (size_t)d * (BB * 1024) + b * 1024;
#pragma unroll
    for (int it = 0; it < 4; it++) {
        int k = t + 256 * it;
        int8_t a, b2;
        quant2(v[it], inv, a, b2);
        g_qpFQ0[dst + k] = a;
        g_qpFQ1[dst + k] = b2;
    }
    if (t == 0) g_sQPF[b * DD + d] = mx / 127.0f;
}

__global__ void q1024_kernel() {
    int i = blockIdx.x * blockDim.x + threadIdx.x;
    if (i < BB * DD) {
        int b = i >> 8, d = i & 255;
        g_q1024[i] = g_qpT[(size_t)d * (BB * NQ) + b * 2048 + 1024];
    }
}

// G3 combine + quantize: qf = part0+part1+bq+(-1)^m q1024; grid (MP, BB), 256 thr
__global__ void g3combineq_kernel(const float* __restrict__ op,
                                  const float* __restrict__ bq) {
    __shared__ float red[8];
    int m = blockIdx.x, b = blockIdx.y, d = threadIdx.x;
    size_t idx = ((size_t)b * MP + m) * DD + d;
    float fx = g_q1024[b * DD + d];
    float v = op[idx] + op[idx + (size_t)8 * MP * DD] + bq[d] + ((m & 1) ? -fx : fx);
    float mx = fmaxf(blockmax256(fabsf(v), red), 1e-30f);
    int8_t a, b2;
    quant2(v, 127.0f / mx, a, b2);
    g_qfQ0[idx] = a;
    g_qfQ1[idx] = b2;
    if (d == 0) g_sQF[b * MP + m] = mx / 127.0f;
}

// ---------------------------------------------------------------------------
// 2-plane int8 mma.sync GEMM: D[m,n] = sA[m]*sB[n]*(acc0 + acc1/256) (+bias[n])
// CTA 128x128, kc=128, 512 threads, 16 warps as 4m x 4n of 32x32 warp tiles,
// k32 IMMA steps.  SPLITK: bz = b + 8*ks, data k offset = ks*K.
// ---------------------------------------------------------------------------
template<int SPLITK>
__global__ void __launch_bounds__(512, 1)
igemm(const int8_t* __restrict__ A0, const int8_t* __restrict__ A1,
      size_t sAb, int rA, const float* __restrict__ sAv, int sAs,
      const int8_t* __restrict__ B0, const int8_t* __restrict__ B1,
      size_t sBb, int rB, const float* __restrict__ sBv, int sBs,
      const float* __restrict__ bias,
      float* __restrict__ D, size_t sD, int oS, int K)
{
    extern __shared__ char sm[];
    const unsigned smb = smem_u32(sm);
    const int tid = threadIdx.x;
    const int lane = tid & 31;
    const int wid = tid >> 5;
    const int m0 = blockIdx.y * 128;
    const int n0 = blockIdx.x * 128;
    const int bz = blockIdx.z;
    const int b  = SPLITK ? (bz & 7) : bz;
    const int koff = SPLITK ? (bz >> 3) * K : 0;
    const int wm = (wid & 3) * 32;
    const int wn = (wid >> 2) * 32;
    const int l15 = lane & 15;
    const int lh = lane >> 4;

    const int8_t* A0b = A0 + (size_t)b * sAb + koff;
    const int8_t* A1b = A1 + (size_t)b * sAb + koff;
    const int8_t* B0b = B0 + (size_t)b * sBb + koff;
    const int8_t* B1b = B1 + (size_t)b * sBb + koff;
    const float* sA = sAv + b * sAs + m0;
    const float* sB = sBv + b * sBs + n0;

    int acc0[2][4][4], acc1[2][4][4];
#pragma unroll
    for (int t = 0; t < 2; t++)
#pragma unroll
        for (int j = 0; j < 4; j++)
#pragma unroll
            for (int i = 0; i < 4; i++) { acc0[t][j][i] = 0; acc1[t][j][i] = 0; }

    const int rw = tid >> 3, ch = tid & 7;

    auto ISSUE = [&](int c) {
        const int ke = (c << 7) + ch * 16;
        const unsigned sb = smb + (c & 1) * 65536;
#pragma unroll
        for (int it = 0; it < 2; it++) {
            int r = rw + it * 64;
            unsigned so = sb + r * 128 + ((ch ^ (r & 7)) << 4);
            size_t ga = (size_t)(m0 + r) * rA + ke;
            size_t gb = (size_t)(n0 + r) * rB + ke;
            cpa(so,         A0b + ga);
            cpa(so + 16384, A1b + ga);
            cpa(so + 32768, B0b + gb);
            cpa(so + 49152, B1b + gb);
        }
        asm volatile("cp.async.commit_group;" ::: "memory");
    };

    const int NC = K >> 7;
    ISSUE(0);
#pragma unroll 1
    for (int c = 0; c < NC; c++) {
        if (c + 1 < NC) {
            ISSUE(c + 1);
            asm volatile("cp.async.wait_group 1;" ::: "memory");
        } else {
            asm volatile("cp.async.wait_group 0;" ::: "memory");
        }
        __syncthreads();
        const unsigned ab = smb + (c & 1) * 65536;
#pragma unroll
        for (int ks = 0; ks < 4; ks++) {
            const unsigned cc = (unsigned)(ks * 2 + lh);
            unsigned A0f[2][4], A1f[2][4], B0f[2][4], B1f[2][4];
#pragma unroll
            for (int t = 0; t < 2; t++) {
                int row = wm + 16 * t + l15;
                unsigned so = ab + row * 128 + ((cc ^ (row & 7)) << 4);
                ldsm4(A0f[t], so);
                ldsm4(A1f[t], so + 16384);
            }
#pragma unroll
            for (int u = 0; u < 2; u++) {
                int row = wn + 16 * u + l15;
                unsigned so = ab + 32768 + row * 128 + ((cc ^ (row & 7)) << 4);
                ldsm4(B0f[u], so);
                ldsm4(B1f[u], so + 16384);
            }
            // pass 1: q0*q0 -> acc0
#pragma unroll
            for (int t = 0; t < 2; t++)
#pragma unroll
                for (int u = 0; u < 2; u++)
#pragma unroll
                    for (int s = 0; s < 2; s++)
                        imma16832(acc0[t][u * 2 + s], A0f[t], B0f[u][s], B0f[u][2 + s]);
            // pass 2: q0*q1 -> acc1
#pragma unroll
            for (int t = 0; t < 2; t++)
#pragma unroll
                for (int u = 0; u < 2; u++)
#pragma unroll
                    for (int s = 0; s < 2; s++)
                        imma16832(acc1[t][u * 2 + s], A0f[t], B1f[u][s], B1f[u][2 + s]);
            // pass 3: q1*q0 -> acc1
#pragma unroll
            for (int t = 0; t < 2; t++)
#pragma unroll
                for (int u = 0; u < 2; u++)
#pragma unroll
                    for (int s = 0; s < 2; s++)
                        imma16832(acc1[t][u * 2 + s], A1f[t], B0f[u][s], B0f[u][2 + s]);
        }
        __syncthreads();
    }

    // ---- epilogue ----
#pragma unroll
    for (int t = 0; t < 2; t++) {
        int r0 = wm + 16 * t + (lane >> 2);
        float sa0 = sA[r0], sa1 = sA[r0 + 8];
#pragma unroll
        for (int j = 0; j < 4; j++) {
            int col = wn + 8 * j + 2 * (lane & 3);
            float sb0 = sB[col], sb1 = sB[col + 1];
            float b0v = 0.0f, b1v = 0.0f;
            if (bias) { b0v = __ldg(&bias[n0 + col]); b1v = __ldg(&bias[n0 + col + 1]); }
            const float W = 0.00390625f;   // 1/256
            float v0 = sa0 * sb0 * ((float)acc0[t][j][0] + (float)acc1[t][j][0] * W) + b0v;
            float v1 = sa0 * sb1 * ((float)acc0[t][j][1] + (float)acc1[t][j][1] * W) + b1v;
            float v2 = sa1 * sb0 * ((float)acc0[t][j][2] + (float)acc1[t][j][2] * W) + b0v;
            float v3 = sa1 * sb1 * ((float)acc0[t][j][3] + (float)acc1[t][j][3] * W) + b1v;
            float* Dp = D + bz * sD;
            *(float2*)(Dp + (size_t)(m0 + r0) * oS + n0 + col) = make_float2(v0, v1);
            *(float2*)(Dp + (size_t)(m0 + r0 + 8) * oS + n0 + col) = make_float2(v2, v3);
        }
    }
}

// ---------------------------------------------------------------------------
// Row softmax over NK with scale 1/16; emits probs as 2-plane int8 + scale
// ---------------------------------------------------------------------------
__global__ void softmaxq_kernel(const float* __restrict__ s) {
    size_t row = blockIdx.x;
    const float* p = s + row * (size_t)NK;
    int t = threadIdx.x;
    float v[8];
#pragma unroll
    for (int i = 0; i < 8; i++) v[i] = p[t + 256 * i] * 0.0625f;
    float mx = v[0];
#pragma unroll
    for (int i = 1; i < 8; i++) mx = fmaxf(mx, v[i]);
#pragma unroll
    for (int o = 16; o > 0; o >>= 1) mx = fmaxf(mx, __shfl_xor_sync(0xffffffffu, mx, o));
    __shared__ float redm[8], reds[8];
    if ((t & 31) == 0) redm[t >> 5] = mx;
    __syncthreads();
    float m2 = redm[0];
#pragma unroll
    for (int i = 1; i < 8; i++) m2 = fmaxf(m2, redm[i]);
    float sum = 0.0f;
#pragma unroll
    for (int i = 0; i < 8; i++) { v[i] = __expf(v[i] - m2); sum += v[i]; }
#pragma unroll
    for (int o = 16; o > 0; o >>= 1) sum += __shfl_xor_sync(0xffffffffu, sum, o);
    if ((t & 31) == 0) reds[t >> 5] = sum;
    __syncthreads();
    float s2 = 0.0f;
#pragma unroll
    for (int i = 0; i < 8; i++) s2 += reds[i];
    float inv = 1.0f / s2;
    size_t base = row * (size_t)NK + t;
    // p_k = v_k * inv; scale s_p = inv/127 -> x = p/s_p = 127*v_k
#pragma unroll
    for (int i = 0; i < 8; i++) {
        int8_t a, b2;
        quant2(v[i], 127.0f, a, b2);
        g_pQ0[base + 256 * i] = a;
        g_pQ1[base + 256 * i] = b2;
    }
    if (t == 0) g_sP[row] = inv * (1.0f / 127.0f);
}

// ---------------------------------------------------------------------------
// final combine: split-K partials + mirror rows out[b][2048-m] = out[b][m]
// ---------------------------------------------------------------------------
__global__ void combine_kernel(const float* __restrict__ op, float* __restrict__ out) {
    int m = blockIdx.x, b = blockIdx.y, d = threadIdx.x;
    size_t src = ((size_t)b * MP + m) * DD + d;
    float v = op[src] + op[src + (size_t)8 * MP * DD];
    out[((size_t)b * NQ + m) * DD + d] = v;
    if (m >= 1 && m <= 1023)
        out[((size_t)b * NQ + 2048 - m) * DD + d] = v;
}

// ---------------------------------------------------------------------------
extern "C" void kernel_launch(void* const* d_in, const int* in_sizes, int n_in,
                              void* d_out, int out_size) {
    const float* query = (const float*)d_in[0];
    const float* key   = (const float*)d_in[1];
    const float* Wq    = (const float*)d_in[2];
    const float* bq    = (const float*)d_in[3];
    const float* Wk    = (const float*)d_in[4];
    const float* bk    = (const float*)d_in[5];
    float* out = (float*)d_out;

#define SYM(p, s) void* p; cudaGetSymbolAddress(&p, s)
    SYM(CQ0, g_CQ0);   SYM(CQ1, g_CQ1);   SYM(sC, g_sC);
    SYM(qQ0, g_qQ0);   SYM(qQ1, g_qQ1);   SYM(sQ, g_sQ);
    SYM(kQ0, g_kQ0);   SYM(kQ1, g_kQ1);   SYM(sK, g_sK);
    SYM(wqQ0, g_wqQ0); SYM(wqQ1, g_wqQ1); SYM(sWQ, g_sWQ);
    SYM(wkQ0, g_wkQ0); SYM(wkQ1, g_wkQ1); SYM(sWK, g_sWK);
    SYM(qpT, g_qpT);
    SYM(qpFQ0, g_qpFQ0); SYM(qpFQ1, g_qpFQ1); SYM(sQPF, g_sQPF);
    SYM(kpf, g_kpf);
    SYM(kpQ0, g_kpQ0); SYM(kpQ1, g_kpQ1); SYM(sKP, g_sKP);
    SYM(qfQ0, g_qfQ0); SYM(qfQ1, g_qfQ1); SYM(sQF, g_sQF);
    SYM(vTf, g_vTf);
    SYM(vTQ0, g_vTQ0); SYM(vTQ1, g_vTQ1); SYM(sVT, g_sVT);
    SYM(sc, g_scores);
    SYM(pQ0, g_pQ0);   SYM(pQ1, g_pQ1);   SYM(sP, g_sP);
    SYM(op, g_op);
#undef SYM

    cudaFuncSetAttribute((const void*)igemm<0>, cudaFuncAttributeMaxDynamicSharedMemorySize, SMI_BYTES);
    cudaFuncSetAttribute((const void*)igemm<1>, cudaFuncAttributeMaxDynamicSharedMemorySize, SMI_BYTES);

    // preps: quantize inputs, cos matrix, transpose value
    cinitq_kernel<<<MP, 256>>>();
    rowquant_kernel<<<BB * NQ, 256>>>(query, (int8_t*)qQ0, (int8_t*)qQ1, (float*)sQ, DD);
    rowquant_kernel<<<BB * NK, 256>>>(key,   (int8_t*)kQ0, (int8_t*)kQ1, (float*)sK, DD);
    rowquant_kernel<<<DD, 256>>>(Wq, (int8_t*)wqQ0, (int8_t*)wqQ1, (float*)sWQ, DD);
    rowquant_kernel<<<DD, 256>>>(Wk, (int8_t*)wkQ0, (int8_t*)wkQ1, (float*)sWK, DD);
    transpose_kernel<<<dim3(NK / 32, DD / 32, BB), dim3(32, 8)>>>(key);
    rowquant_kernel<<<BB * DD, 256>>>((const float*)vTf, (int8_t*)vTQ0, (int8_t*)vTQ1,
                                      (float*)sVT, NK);

    // G1: qprojT[d, bm] = Wq @ query^T    (M=256, N=16384, K=256)
    igemm<0><<<dim3(128, 2, 1), 512, SMI_BYTES>>>(
        (int8_t*)wqQ0, (int8_t*)wqQ1, 0, DD, (float*)sWQ, 0,
        (int8_t*)qQ0, (int8_t*)qQ1, 0, DD, (float*)sQ, 0,
        nullptr, (float*)qpT, 0, BB * NQ, DD);
    // fold + quantize, row-1024 extraction
    foldq_kernel<<<dim3(DD, BB), 256>>>();
    q1024_kernel<<<(BB * DD + 255) / 256, 256>>>();

    // G2: kproj = key @ Wk^T + bk         (M=16384, N=256, K=256), then rowquant
    igemm<0><<<dim3(2, 128, 1), 512, SMI_BYTES>>>(
        (int8_t*)kQ0, (int8_t*)kQ1, 0, DD, (float*)sK, 0,
        (int8_t*)wkQ0, (int8_t*)wkQ1, 0, DD, (float*)sWK, 0,
        bk, (float*)kpf, 0, DD, DD);
    rowquant_kernel<<<BB * NK, 256>>>((const float*)kpf, (int8_t*)kpQ0, (int8_t*)kpQ1,
                                      (float*)sKP, DD);

    // G3: qfft partials = Cfold @ qpF^T, split-K=2 (per bz: M=1152, N=256, K=512)
    igemm<1><<<dim3(2, 9, 16), 512, SMI_BYTES>>>(
        (int8_t*)CQ0, (int8_t*)CQ1, 0, 1024, (float*)sC, 0,
        (int8_t*)qpFQ0, (int8_t*)qpFQ1, 1024, BB * 1024, (float*)sQPF, DD,
        nullptr, (float*)op, (size_t)MP * DD, DD, 512);
    g3combineq_kernel<<<dim3(MP, BB), 256>>>((const float*)op, bq);

    // G4: scores = qfft @ kproj^T         (per b: M=1152, N=2048, K=256)
    igemm<0><<<dim3(16, 9, BB), 512, SMI_BYTES>>>(
        (int8_t*)qfQ0, (int8_t*)qfQ1, (size_t)MP * DD, DD, (float*)sQF, MP,
        (int8_t*)kpQ0, (int8_t*)kpQ1, (size_t)NK * DD, DD, (float*)sKP, NK,
        nullptr, (float*)sc, (size_t)MP * NK, NK, DD);
    // softmax -> int8 probs
    softmaxq_kernel<<<BB * MP, 256>>>((const float*)sc);
    // G5: partial out = probs @ vT^T, split-K=2 (per bz: M=1152, N=256, K=1024)
    igemm<1><<<dim3(2, 9, 16), 512, SMI_BYTES>>>(
        (int8_t*)pQ0, (int8_t*)pQ1, (size_t)MP * NK, NK, (float*)sP, MP,
        (int8_t*)vTQ0, (int8_t*)vTQ1, (size_t)DD * NK, NK, (float*)sVT, DD,
        nullptr, (float*)op, (size_t)MP * DD, DD, 1024);
    // combine partials + mirror
    combine_kernel<<<dim3(1025, BB), 256>>>((const float*)op, out);
}

// round 10
// speedup vs baseline: 2.7487x; 2.7487x over previous
#include <cuda_runtime.h>
#include <cuda_bf16.h>
#include <cuda_fp16.h>
#include <math.h>
#include <stdint.h>

#define BB 8
#define NQ 2048
#define NK 2048
#define DD 256
#define MP 1152              // padded half-row count (9*128), rows 0..1024 real
#define KF 1088              // folded K (1025 real cols + pad), 17*64
#define NF (BB * KF)         // 8704 = 34*256
typedef __nv_bfloat16 bf16;

// ---------------- static gmem scratch ----------------
__device__ __align__(256) bf16 g_CH[MP * KF], g_CL[MP * KF];     // cos matrix (cols>1024 = 0)
__device__ __align__(256) bf16 g_qFh[NF * DD], g_qFl[NF * DD];   // folded query split
__device__ __align__(256) bf16 g_kH[BB * NK * DD], g_kL[BB * NK * DD];
__device__ __align__(256) bf16 g_wqH[DD * DD], g_wqL[DD * DD];
__device__ __align__(256) bf16 g_wkH[DD * DD], g_wkL[DD * DD];
__device__ __align__(256) bf16 g_qpFTH[DD * NF], g_qpFTL[DD * NF]; // folded qprojT [256][8704]
__device__ __align__(256) bf16 g_kpH[BB * NK * DD], g_kpL[BB * NK * DD];
__device__ __align__(256) bf16 g_qfH[BB * MP * DD], g_qfL[BB * MP * DD];
__device__ __align__(256) __half g_vT[BB * DD * NK];              // key^T fp16 (value)
__device__ float g_scores[(size_t)BB * MP * NK];
__device__ __align__(256) __half g_pF[(size_t)BB * MP * NK];      // probs fp16
__device__ float g_op[16 * MP * DD];                              // split-K partials

// ---------------- helpers ----------------
__device__ __forceinline__ unsigned smem_u32(const void* p) {
    unsigned a;
    asm("{ .reg .u64 t; cvta.to.shared.u64 t, %1; cvt.u32.u64 %0, t; }"
        : "=r"(a) : "l"(p));
    return a;
}
__device__ __forceinline__ void ldsm4(unsigned r[4], unsigned addr) {
    asm volatile("ldmatrix.sync.aligned.m8n8.x4.shared.b16 {%0,%1,%2,%3}, [%4];"
                 : "=r"(r[0]), "=r"(r[1]), "=r"(r[2]), "=r"(r[3]) : "r"(addr));
}
__device__ __forceinline__ void mma_bf16(float d[4], const unsigned a[4],
                                         unsigned b0, unsigned b1) {
    asm volatile(
        "mma.sync.aligned.m16n8k16.row.col.f32.bf16.bf16.f32 "
        "{%0,%1,%2,%3}, {%4,%5,%6,%7}, {%8,%9}, {%0,%1,%2,%3};"
        : "+f"(d[0]), "+f"(d[1]), "+f"(d[2]), "+f"(d[3])
        : "r"(a[0]), "r"(a[1]), "r"(a[2]), "r"(a[3]), "r"(b0), "r"(b1));
}
__device__ __forceinline__ void mma_f16(float d[4], const unsigned a[4],
                                        unsigned b0, unsigned b1) {
    asm volatile(
        "mma.sync.aligned.m16n8k16.row.col.f32.f16.f16.f32 "
        "{%0,%1,%2,%3}, {%4,%5,%6,%7}, {%8,%9}, {%0,%1,%2,%3};"
        : "+f"(d[0]), "+f"(d[1]), "+f"(d[2]), "+f"(d[3])
        : "r"(a[0]), "r"(a[1]), "r"(a[2]), "r"(a[3]), "r"(b0), "r"(b1));
}
__device__ __forceinline__ void cpa(unsigned dst, const void* src) {
    asm volatile("cp.async.cg.shared.global [%0], [%1], 16;" :: "r"(dst), "l"(src));
}

// ---------------- prep kernels ----------------
__global__ void split_kernel(const float* __restrict__ x, bf16* __restrict__ h,
                             bf16* __restrict__ l, int n) {
    int i = blockIdx.x * blockDim.x + threadIdx.x;
    if (i < n) {
        float v = x[i];
        bf16 hv = __float2bfloat16(v);
        h[i] = hv;
        l[i] = __float2bfloat16(v - __bfloat162float(hv));
    }
}

// cos matrix C[m][k]: cos(2*pi*m*k/2048) for k<=1024 (incl. k=1024 -> (-1)^m), 0 beyond
__global__ void cinit_kernel() {
    int m = blockIdx.x;
    for (int k = threadIdx.x; k < KF; k += 256) {
        float c = (k <= 1024)
                    ? cospif((float)((m * k) & 2047) * (1.0f / 1024.0f))
                    : 0.0f;
        bf16 h = __float2bfloat16(c);
        g_CH[m * KF + k] = h;
        g_CL[m * KF + k] = __float2bfloat16(c - __bfloat162float(h));
    }
}

// fold query rows before projection: qF[b,k] = q[b,k] + q[b,2048-k] (1<=k<=1023),
// qF[b,0]=q[b,0], qF[b,1024]=q[b,1024], rows 1025..1087 zero.  grid (KF, BB), 256 thr=d
__global__ void foldsplit_kernel(const float* __restrict__ query) {
    int k = blockIdx.x, b = blockIdx.y, d = threadIdx.x;
    float v = 0.0f;
    if (k <= 1024) {
        const float* qb = query + (size_t)b * NQ * DD;
        v = qb[(size_t)k * DD + d];
        if (k >= 1 && k <= 1023) v += qb[(size_t)(2048 - k) * DD + d];
    }
    size_t idx = ((size_t)b * KF + k) * DD + d;
    bf16 h = __float2bfloat16(v);
    g_qFh[idx] = h;
    g_qFl[idx] = __float2bfloat16(v - __bfloat162float(h));
}

// key^T as fp16 (value operand for PV)
__global__ void transpose_kernel(const float* __restrict__ key) {
    __shared__ float ts[32][33];
    int b = blockIdx.z, n0 = blockIdx.x * 32, d0 = blockIdx.y * 32;
    const float* kb = key + (size_t)b * NK * DD;
#pragma unroll
    for (int i = 0; i < 4; i++) {
        int r = threadIdx.y + i * 8;
        ts[r][threadIdx.x] = kb[(size_t)(n0 + r) * DD + d0 + threadIdx.x];
    }
    __syncthreads();
#pragma unroll
    for (int i = 0; i < 4; i++) {
        int d = threadIdx.y + i * 8;
        g_vT[(size_t)b * DD * NK + (size_t)(d0 + d) * NK + n0 + threadIdx.x] =
            __float2half_rn(ts[threadIdx.x][d]);
    }
}

// ---------------------------------------------------------------------------
// Split-bf16 mma.sync GEMM (R5-proven).  D[m,n] = sum_k A[m,k]*B[n,k] (+bias).
// CTA 128m x NTn, kc=64, 256 thr. NT=256: 2m x 4n warps (64x64). NT=128: 4m x 2n (32x64).
// OUT: 0 fp32 D, 1 bf16 hi/lo.
// ---------------------------------------------------------------------------
template<int OUT, int NT>
__global__ void __launch_bounds__(256, 1)
gemm_kernel(const bf16* __restrict__ AH, const bf16* __restrict__ AL,
            size_t sA, int rA,
            const bf16* __restrict__ BH, const bf16* __restrict__ BL,
            size_t sB, int rB,
            const float* __restrict__ bias,
            float* __restrict__ D, bf16* __restrict__ DH, bf16* __restrict__ DL,
            size_t sD, int oS, int K)
{
    constexpr int TM   = (NT == 256) ? 4 : 2;
    constexpr int NB   = NT / 32;
    constexpr int BSZ  = NT * 128;
    constexpr int BUFS = 32768 + 2 * BSZ;

    extern __shared__ char sm[];
    const unsigned smb = smem_u32(sm);
    const int tid = threadIdx.x;
    const int lane = tid & 31;
    const int wid = tid >> 5;
    const int m0 = blockIdx.y * 128;
    const int n0 = blockIdx.x * NT;
    const int b  = blockIdx.z;
    const int wm = (NT == 256) ? (wid & 1) * 64 : (wid & 3) * 32;
    const int wn = (NT == 256) ? (wid >> 1) * 64 : (wid >> 2) * 64;
    const int l15 = lane & 15;
    const int lh = lane >> 4;

    const bf16* AHb = AH + b * sA;
    const bf16* ALb = AL + b * sA;
    const bf16* BHb = BH + b * sB;
    const bf16* BLb = BL + b * sB;

    float acc[TM][8][4];
#pragma unroll
    for (int t = 0; t < TM; t++)
#pragma unroll
        for (int j = 0; j < 8; j++)
#pragma unroll
            for (int i = 0; i < 4; i++) acc[t][j][i] = 0.0f;

    const int rw = tid >> 3, ch = tid & 7;

    auto ISSUE = [&](int c) {
        const int ke = (c << 6) + ch * 8;
        const unsigned bufb = smb + (c & 1) * BUFS;
#pragma unroll
        for (int it = 0; it < 4; it++) {
            int r = rw + it * 32;
            unsigned so = bufb + r * 128 + ((ch ^ (r & 7)) << 4);
            size_t go = (size_t)(m0 + r) * rA + ke;
            cpa(so, AHb + go);
            cpa(so + 16384, ALb + go);
        }
#pragma unroll
        for (int it = 0; it < NB; it++) {
            int r = rw + it * 32;
            unsigned so = bufb + 32768 + r * 128 + ((ch ^ (r & 7)) << 4);
            size_t go = (size_t)(n0 + r) * rB + ke;
            cpa(so, BHb + go);
            cpa(so + BSZ, BLb + go);
        }
        asm volatile("cp.async.commit_group;" ::: "memory");
    };

    auto COMPUTE = [&](int buf) {
        const unsigned ab = smb + buf * BUFS;
#pragma unroll
        for (int ks = 0; ks < 4; ks++) {
            unsigned Ah[TM][4], Al[TM][4], Bh[4][4], Bl[4][4];
#pragma unroll
            for (int t = 0; t < TM; t++) {
                int row = wm + 16 * t + l15;
                unsigned so = ab + row * 128 + (((ks * 2 + lh) ^ (row & 7)) << 4);
                ldsm4(Ah[t], so);
                ldsm4(Al[t], so + 16384);
            }
#pragma unroll
            for (int nt = 0; nt < 4; nt++) {
                int row = wn + 16 * nt + l15;
                unsigned so = ab + 32768 + row * 128 +
                              (((ks * 2 + lh) ^ (row & 7)) << 4);
                ldsm4(Bh[nt], so);
                ldsm4(Bl[nt], so + BSZ);
            }
#pragma unroll
            for (int t = 0; t < TM; t++)
#pragma unroll
                for (int nt = 0; nt < 4; nt++)
#pragma unroll
                    for (int s = 0; s < 2; s++) {
                        int j = nt * 2 + s;
                        mma_bf16(acc[t][j], Ah[t], Bh[nt][s], Bh[nt][2 + s]);
                        mma_bf16(acc[t][j], Ah[t], Bl[nt][s], Bl[nt][2 + s]);
                        mma_bf16(acc[t][j], Al[t], Bh[nt][s], Bh[nt][2 + s]);
                    }
        }
    };

    const int NC = K >> 6;
    ISSUE(0);
#pragma unroll 1
    for (int c = 0; c < NC; c++) {
        if (c + 1 < NC) {
            ISSUE(c + 1);
            asm volatile("cp.async.wait_group 1;" ::: "memory");
        } else {
            asm volatile("cp.async.wait_group 0;" ::: "memory");
        }
        __syncthreads();
        COMPUTE(c & 1);
        __syncthreads();
    }

    // ---- epilogue ----
#pragma unroll
    for (int t = 0; t < TM; t++) {
#pragma unroll
        for (int j = 0; j < 8; j++) {
            int r0 = m0 + wm + 16 * t + (lane >> 2);
            int col = n0 + wn + 8 * j + 2 * (lane & 3);
            float b0v = 0.0f, b1v = 0.0f;
            if (bias) { b0v = __ldg(&bias[col]); b1v = __ldg(&bias[col + 1]); }
            float v0 = acc[t][j][0] + b0v, v1 = acc[t][j][1] + b1v;
            float v2 = acc[t][j][2] + b0v, v3 = acc[t][j][3] + b1v;
            if (OUT == 0) {
                float* Dp = D + b * sD;
                *(float2*)(Dp + (size_t)r0 * oS + col) = make_float2(v0, v1);
                *(float2*)(Dp + (size_t)(r0 + 8) * oS + col) = make_float2(v2, v3);
            } else {
                bf16* Hp = DH + b * sD;
                bf16* Lp = DL + b * sD;
                __nv_bfloat162 h01, h23, l01, l23;
                h01.x = __float2bfloat16(v0); h01.y = __float2bfloat16(v1);
                h23.x = __float2bfloat16(v2); h23.y = __float2bfloat16(v3);
                l01.x = __float2bfloat16(v0 - __bfloat162float(h01.x));
                l01.y = __float2bfloat16(v1 - __bfloat162float(h01.y));
                l23.x = __float2bfloat16(v2 - __bfloat162float(h23.x));
                l23.y = __float2bfloat16(v3 - __bfloat162float(h23.y));
                *(__nv_bfloat162*)(Hp + (size_t)r0 * oS + col) = h01;
                *(__nv_bfloat162*)(Lp + (size_t)r0 * oS + col) = l01;
                *(__nv_bfloat162*)(Hp + (size_t)(r0 + 8) * oS + col) = h23;
                *(__nv_bfloat162*)(Lp + (size_t)(r0 + 8) * oS + col) = l23;
            }
        }
    }
}

// ---------------------------------------------------------------------------
// Single-plane fp16 GEMM for PV (post-softmax; error amplification ~1).
// D[m,n] = sum_k A[m,k]*B[n,k], fp32 accum.  CTA 128x128, kc=64, 256 thr,
// 8 warps as 4m x 2n of 32x64 tiles.  Split-K=2: bz = b + 8*ks.
// ---------------------------------------------------------------------------
__global__ void __launch_bounds__(256, 1)
hgemm(const __half* __restrict__ A, size_t sAb, int rA,
      const __half* __restrict__ B, size_t sBb, int rB,
      float* __restrict__ D, size_t sD, int oS, int K)
{
    extern __shared__ char sm[];
    const unsigned smb = smem_u32(sm);
    const int tid = threadIdx.x;
    const int lane = tid & 31;
    const int wid = tid >> 5;
    const int m0 = blockIdx.y * 128;
    const int n0 = blockIdx.x * 128;
    const int bz = blockIdx.z;
    const int b  = bz & 7;
    const int koff = (bz >> 3) * K;
    const int wm = (wid & 3) * 32;
    const int wn = (wid >> 2) * 64;
    const int l15 = lane & 15;
    const int lh = lane >> 4;

    const __half* Ab = A + (size_t)b * sAb + koff;
    const __half* Bb = B + (size_t)b * sBb + koff;

    float acc[2][8][4];
#pragma unroll
    for (int t = 0; t < 2; t++)
#pragma unroll
        for (int j = 0; j < 8; j++)
#pragma unroll
            for (int i = 0; i < 4; i++) acc[t][j][i] = 0.0f;

    const int rw = tid >> 3, ch = tid & 7;

    auto ISSUE = [&](int c) {
        const int ke = (c << 6) + ch * 8;
        const unsigned sb = smb + (c & 1) * 32768;
#pragma unroll
        for (int it = 0; it < 4; it++) {
            int r = rw + it * 32;
            unsigned so = sb + r * 128 + ((ch ^ (r & 7)) << 4);
            cpa(so, Ab + (size_t)(m0 + r) * rA + ke);
            cpa(so + 16384, Bb + (size_t)(n0 + r) * rB + ke);
        }
        asm volatile("cp.async.commit_group;" ::: "memory");
    };

    const int NC = K >> 6;
    ISSUE(0);
#pragma unroll 1
    for (int c = 0; c < NC; c++) {
        if (c + 1 < NC) {
            ISSUE(c + 1);
            asm volatile("cp.async.wait_group 1;" ::: "memory");
        } else {
            asm volatile("cp.async.wait_group 0;" ::: "memory");
        }
        __syncthreads();
        const unsigned ab = smb + (c & 1) * 32768;
#pragma unroll
        for (int ks = 0; ks < 4; ks++) {
            const unsigned cc = (unsigned)(ks * 2 + lh);
            unsigned Af[2][4], Bf[4][4];
#pragma unroll
            for (int t = 0; t < 2; t++) {
                int row = wm + 16 * t + l15;
                ldsm4(Af[t], ab + row * 128 + ((cc ^ (row & 7)) << 4));
            }
#pragma unroll
            for (int nt = 0; nt < 4; nt++) {
                int row = wn + 16 * nt + l15;
                ldsm4(Bf[nt], ab + 16384 + row * 128 + ((cc ^ (row & 7)) << 4));
            }
#pragma unroll
            for (int t = 0; t < 2; t++)
#pragma unroll
                for (int nt = 0; nt < 4; nt++)
#pragma unroll
                    for (int s = 0; s < 2; s++)
                        mma_f16(acc[t][nt * 2 + s], Af[t], Bf[nt][s], Bf[nt][2 + s]);
        }
        __syncthreads();
    }

    // ---- epilogue ----
    float* Dp = D + (size_t)bz * sD;
#pragma unroll
    for (int t = 0; t < 2; t++) {
#pragma unroll
        for (int j = 0; j < 8; j++) {
            int r0 = m0 + wm + 16 * t + (lane >> 2);
            int col = n0 + wn + 8 * j + 2 * (lane & 3);
            *(float2*)(Dp + (size_t)r0 * oS + col) =
                make_float2(acc[t][j][0], acc[t][j][1]);
            *(float2*)(Dp + (size_t)(r0 + 8) * oS + col) =
                make_float2(acc[t][j][2], acc[t][j][3]);
        }
    }
}

// ---------------------------------------------------------------------------
// Row softmax over NK with scale 1/16; emits probs as fp16
// ---------------------------------------------------------------------------
__global__ void softmax_kernel(const float* __restrict__ s, __half* __restrict__ pF) {
    size_t row = blockIdx.x;
    const float* p = s + row * (size_t)NK;
    int t = threadIdx.x;
    float v[8];
#pragma unroll
    for (int i = 0; i < 8; i++) v[i] = p[t + 256 * i] * 0.0625f;
    float mx = v[0];
#pragma unroll
    for (int i = 1; i < 8; i++) mx = fmaxf(mx, v[i]);
#pragma unroll
    for (int o = 16; o > 0; o >>= 1) mx = fmaxf(mx, __shfl_xor_sync(0xffffffffu, mx, o));
    __shared__ float redm[8], reds[8];
    if ((t & 31) == 0) redm[t >> 5] = mx;
    __syncthreads();
    float m2 = redm[0];
#pragma unroll
    for (int i = 1; i < 8; i++) m2 = fmaxf(m2, redm[i]);
    float sum = 0.0f;
#pragma unroll
    for (int i = 0; i < 8; i++) { v[i] = __expf(v[i] - m2); sum += v[i]; }
#pragma unroll
    for (int o = 16; o > 0; o >>= 1) sum += __shfl_xor_sync(0xffffffffu, sum, o);
    if ((t & 31) == 0) reds[t >> 5] = sum;
    __syncthreads();
    float s2 = 0.0f;
#pragma unroll
    for (int i = 0; i < 8; i++) s2 += reds[i];
    float inv = 1.0f / s2;
    size_t base = row * (size_t)NK + t;
#pragma unroll
    for (int i = 0; i < 8; i++)
        pF[base + 256 * i] = __float2half_rn(v[i] * inv);
}

// ---------------------------------------------------------------------------
// final combine: split-K partials + mirror rows out[b][2048-m] = out[b][m]
// ---------------------------------------------------------------------------
__global__ void combine_kernel(const float* __restrict__ op, float* __restrict__ out) {
    int m = blockIdx.x, b = blockIdx.y, d = threadIdx.x;
    size_t src = ((size_t)b * MP + m) * DD + d;
    float v = op[src] + op[src + (size_t)8 * MP * DD];
    out[((size_t)b * NQ + m) * DD + d] = v;
    if (m >= 1 && m <= 1023)
        out[((size_t)b * NQ + 2048 - m) * DD + d] = v;
}

// ---------------------------------------------------------------------------
extern "C" void kernel_launch(void* const* d_in, const int* in_sizes, int n_in,
                              void* d_out, int out_size) {
    const float* query = (const float*)d_in[0];
    const float* key   = (const float*)d_in[1];
    const float* Wq    = (const float*)d_in[2];
    const float* bq    = (const float*)d_in[3];
    const float* Wk    = (const float*)d_in[4];
    const float* bk    = (const float*)d_in[5];
    float* out = (float*)d_out;

#define SYM(p, s) void* p; cudaGetSymbolAddress(&p, s)
    SYM(CH, g_CH);     SYM(CL, g_CL);
    SYM(qFh, g_qFh);   SYM(qFl, g_qFl);
    SYM(kH, g_kH);     SYM(kL, g_kL);
    SYM(wqH, g_wqH);   SYM(wqL, g_wqL);
    SYM(wkH, g_wkH);   SYM(wkL, g_wkL);
    SYM(qpFTH, g_qpFTH); SYM(qpFTL, g_qpFTL);
    SYM(kpH, g_kpH);   SYM(kpL, g_kpL);
    SYM(qfH, g_qfH);   SYM(qfL, g_qfL);
    SYM(vT, g_vT);     SYM(pF, g_pF);
    SYM(sc, g_scores); SYM(op, g_op);
#undef SYM

    const int SM256 = 2 * (32768 + 2 * 256 * 128);   // 196608
    const int SM128 = 2 * (32768 + 2 * 128 * 128);   // 131072
    const int SMH   = 65536;
    cudaFuncSetAttribute((const void*)gemm_kernel<1,256>, cudaFuncAttributeMaxDynamicSharedMemorySize, SM256);
    cudaFuncSetAttribute((const void*)gemm_kernel<0,256>, cudaFuncAttributeMaxDynamicSharedMemorySize, SM256);
    cudaFuncSetAttribute((const void*)gemm_kernel<1,128>, cudaFuncAttributeMaxDynamicSharedMemorySize, SM128);
    cudaFuncSetAttribute((const void*)hgemm, cudaFuncAttributeMaxDynamicSharedMemorySize, SMH);

    // preps
    cinit_kernel<<<MP, 256>>>();
    foldsplit_kernel<<<dim3(KF, BB), 256>>>(query);
    split_kernel<<<16384, 256>>>(key, (bf16*)kH, (bf16*)kL, BB * NK * DD);
    split_kernel<<<256, 256>>>(Wq, (bf16*)wqH, (bf16*)wqL, DD * DD);
    split_kernel<<<256, 256>>>(Wk, (bf16*)wkH, (bf16*)wkL, DD * DD);
    transpose_kernel<<<dim3(NK / 32, DD / 32, BB), dim3(32, 8)>>>(key);

    // G1: qpFT[d, b*KF+k] = Wq @ qFold^T   (M=256, N=8704, K=256)
    gemm_kernel<1,256><<<dim3(NF / 256, 2, 1), 256, SM256>>>(
        (bf16*)wqH, (bf16*)wqL, 0, DD, (bf16*)qFh, (bf16*)qFl, 0, DD,
        nullptr, nullptr, (bf16*)qpFTH, (bf16*)qpFTL, 0, NF, DD);
    // G2: kproj = key @ Wk^T + bk          (M=16384, N=256, K=256)
    gemm_kernel<1,256><<<dim3(1, 128, 1), 256, SM256>>>(
        (bf16*)kH, (bf16*)kL, 0, DD, (bf16*)wkH, (bf16*)wkL, 0, DD,
        bk, nullptr, (bf16*)kpH, (bf16*)kpL, 0, DD, DD);
    // G3: qfft = C @ qpFT^T + bq           (per b: M=1152, N=256, K=1088)
    gemm_kernel<1,128><<<dim3(2, 9, BB), 256, SM128>>>(
        (bf16*)CH, (bf16*)CL, 0, KF, (bf16*)qpFTH, (bf16*)qpFTL, KF, NF,
        bq, nullptr, (bf16*)qfH, (bf16*)qfL, (size_t)MP * DD, DD, KF);
    // G4: scores = qfft @ kproj^T          (per b: M=1152, N=2048, K=256)
    gemm_kernel<0,256><<<dim3(8, 9, BB), 256, SM256>>>(
        (bf16*)qfH, (bf16*)qfL, (size_t)MP * DD, DD,
        (bf16*)kpH, (bf16*)kpL, (size_t)NK * DD, DD,
        nullptr, (float*)sc, nullptr, nullptr, (size_t)MP * NK, NK, DD);
    // softmax -> fp16 probs
    softmax_kernel<<<BB * MP, 256>>>((const float*)sc, (__half*)pF);
    // G5: partial out = probs @ vT^T (fp16 single pass, split-K=2)
    hgemm<<<dim3(2, 9, 16), 256, SMH>>>(
        (const __half*)pF, (size_t)MP * NK, NK,
        (const __half*)vT, (size_t)DD * NK, NK,
        (float*)op, (size_t)MP * DD, DD, 1024);
    // combine partials + mirror
    combine_kernel<<<dim3(1025, BB), 256>>>((const float*)op, out);
}